// round 16
// baseline (speedup 1.0000x reference)
#include <cuda_runtime.h>
#include <cstdint>

// Shapes:
//   x0:     (B=4, N=512, 3)          float32
//   params: (B=4, T=96, N=512, 514)  float32
// d_out = output_view (B,T,N,3) ++ epiparams (B,T,N,514)

#define BB 4
#define TT 96
#define NN 512
#define PROW 514
#define EPSV 1e-8f

#define BLOCKS_PER_GROUP 32
#define THREADS 512
#define WARPS 16
#define OUT_VIEW_ELEMS (BB * TT * NN * 3)   // 589824

// ---- global scratch (static; no allocation) ----
__device__ unsigned g_flag[BB][BLOCKS_PER_GROUP];  // per-block epoch flags
__device__ float    g_xI[2][BB][NN];               // double-buffered I vector

__global__ void reset_kernel() {
    if (threadIdx.x < BB * BLOCKS_PER_GROUP)
        reinterpret_cast<unsigned*>(g_flag)[threadIdx.x] = 0u;
}

__device__ __forceinline__ void load_row(const float* __restrict__ params,
                                         size_t rindex, int lane,
                                         float2 v[8], float& p01) {
    const float* prow = params + rindex * (size_t)PROW;
    p01 = (lane < 2) ? prow[lane] : 0.0f;
    // prow+2 is 8-byte aligned for every row (row stride 2056 B, +8).
    const float2* prow2 = reinterpret_cast<const float2*>(prow + 2);
#pragma unroll
    for (int k = 0; k < 8; ++k) v[k] = prow2[lane + 32 * k];
}

__global__ void __launch_bounds__(THREADS, 1)
ssir_kernel(const float* __restrict__ x0,
            const float* __restrict__ params,
            float* __restrict__ out) {
    __shared__ unsigned s_count;   // block arrival counter (accumulating)

    const int b    = blockIdx.y;
    const int blk  = blockIdx.x;
    const int warp = threadIdx.x >> 5;
    const int lane = threadIdx.x & 31;
    const int n    = blk * WARPS + warp;   // row owned by this warp

    if (threadIdx.x == 0) s_count = 0u;
    __syncthreads();   // only block-wide sync; outside the loop
    const unsigned s_addr =
        (unsigned)__cvta_generic_to_shared(&s_count);

    float* outv = out;                   // output_view region
    float* oute = out + OUT_VIEW_ELEMS;  // epiparams region

    const size_t rbase = ((size_t)b * TT) * NN + (size_t)n;

    // Scan state lives in registers (redundant across lanes).
    const float* xr = x0 + ((size_t)b * NN + n) * 3;
    float S  = xr[0];
    float Iv = xr[1];
    float R  = xr[2];

    // Depth-2 prefetch pipeline.
    float2 v[8], vn[8];
    float p01, p01n;
    load_row(params, rbase, lane, v, p01);
    load_row(params, rbase + NN, lane, vn, p01n);

    for (int t = 0; t < TT; ++t) {
        // ---------- issue prefetch of row t+2 first ----------
        float2 vn2[8];
        float p01n2 = 0.0f;
        if (t + 2 < TT)
            load_row(params, rbase + (size_t)(t + 2) * NN, lane, vn2, p01n2);

        // ---------- shadow work (scan-independent) ----------
        float p0 = __shfl_sync(0xffffffffu, p01, 0);
        float p1 = __shfl_sync(0xffffffffu, p01, 1);
        float beta  = 1.0f / (1.0f + __expf(-p0));
        float gamma = 1.0f / (1.0f + __expf(-p1));

        float m = -1e30f;
#pragma unroll
        for (int k = 0; k < 8; ++k) m = fmaxf(m, fmaxf(v[k].x, v[k].y));
#pragma unroll
        for (int off = 16; off; off >>= 1)
            m = fmaxf(m, __shfl_xor_sync(0xffffffffu, m, off));

        float sum = 0.0f;
#pragma unroll
        for (int k = 0; k < 8; ++k) {
            v[k].x = __expf(v[k].x - m);
            v[k].y = __expf(v[k].y - m);
            sum += v[k].x + v[k].y;
        }
#pragma unroll
        for (int off = 16; off; off >>= 1)
            sum += __shfl_xor_sync(0xffffffffu, sum, off);
        float inv = 1.0f / sum;
#pragma unroll
        for (int k = 0; k < 8; ++k) { v[k].x *= inv; v[k].y *= inv; }

        // Stream out the epiparams row (independent of the scan).
        const size_t rindex = rbase + (size_t)t * NN;
        float* erow = oute + rindex * (size_t)PROW;
        if (lane == 0)
            *reinterpret_cast<float2*>(erow) = make_float2(beta, gamma);
        float2* erow2 = reinterpret_cast<float2*>(erow + 2);
#pragma unroll
        for (int k = 0; k < 8; ++k)
            erow2[lane + 32 * k] = v[k];

        // ---------- per-warp critical path (no block syncs) ----------
        float dot = 0.0f;
        if (t == 0) {
#pragma unroll
            for (int k = 0; k < 8; ++k) {
                int i0 = 2 * (lane + 32 * k);
                float ix = x0[((size_t)b * NN + i0) * 3 + 1];
                float iy = x0[((size_t)b * NN + i0 + 1) * 3 + 1];
                dot += v[k].x * ix + v[k].y * iy;
            }
        } else {
            // Each warp polls all 32 producer flags (coalesced 128-B acquire).
            unsigned r;
            do {
                asm volatile("ld.acquire.gpu.global.u32 %0, [%1];"
                             : "=r"(r) : "l"(&g_flag[b][lane]) : "memory");
            } while (__any_sync(0xffffffffu, r < (unsigned)t));

            const float2* Ip = reinterpret_cast<const float2*>(g_xI[t & 1][b]);
#pragma unroll
            for (int k = 0; k < 8; ++k) {
                float2 iv = Ip[lane + 32 * k];
                dot += v[k].x * iv.x + v[k].y * iv.y;
            }
        }
#pragma unroll
        for (int off = 16; off; off >>= 1)
            dot += __shfl_xor_sync(0xffffffffu, dot, off);
        float infection = dot;

        float Npop = fmaxf(S + Iv + R, EPSV);
        float dS = -((beta * S) / Npop) * infection;
        float gI = gamma * Iv;
        float St = fmaxf(S + dS, 0.0f);
        float It = fmaxf(Iv - dS - gI, 0.0f);
        float Rt = fmaxf(R + gI, 0.0f);
        float scale = Npop / fmaxf(St + It + Rt, EPSV);
        S  = St * scale;
        Iv = It * scale;
        R  = Rt * scale;

        // output_view row: 3 lanes store in parallel
        if (lane < 3) {
            float ov = (lane == 0) ? S : ((lane == 1) ? Iv : R);
            outv[rindex * 3 + lane] = ov;
        }

        // Publish I_{t+1}, then hierarchical arrive:
        //   lane0: st.global I  ->  atom.acq_rel.cta (orders the I store)
        //   16th arriver: st.release.gpu block flag (carries causality).
        if (lane == 0 && t + 1 < TT) {
            g_xI[(t + 1) & 1][b][n] = Iv;
            unsigned old;
            asm volatile("atom.add.acq_rel.cta.shared.u32 %0, [%1], %2;"
                         : "=r"(old) : "r"(s_addr), "r"(1u) : "memory");
            if (old == (unsigned)(WARPS * (t + 1) - 1)) {
                asm volatile("st.release.gpu.global.u32 [%0], %1;"
                             :: "l"(&g_flag[b][blk]), "r"((unsigned)(t + 1))
                             : "memory");
            }
        }

        // Rotate the prefetch pipeline.
#pragma unroll
        for (int k = 0; k < 8; ++k) { v[k] = vn[k]; vn[k] = vn2[k]; }
        p01  = p01n;
        p01n = p01n2;
    }
}

extern "C" void kernel_launch(void* const* d_in, const int* in_sizes, int n_in,
                              void* d_out, int out_size) {
    (void)in_sizes; (void)n_in; (void)out_size;
    const float* x0     = (const float*)d_in[0];
    const float* params = (const float*)d_in[1];
    float* out = (float*)d_out;

    reset_kernel<<<1, 128>>>();

    dim3 grid(BLOCKS_PER_GROUP, BB);
    ssir_kernel<<<grid, THREADS>>>(x0, params, out);
}

// round 17
// speedup vs baseline: 3.7799x; 3.7799x over previous
#include <cuda_runtime.h>
#include <cstdint>

// Shapes:
//   x0:     (B=4, N=512, 3)          float32
//   params: (B=4, T=96, N=512, 514)  float32
// d_out = output_view (B,T,N,3) ++ epiparams (B,T,N,514)

#define BB 4
#define TT 96
#define NN 512
#define PROW 514
#define EPSV 1e-8f

#define BLOCKS_PER_GROUP 32
#define THREADS 512
#define OUT_VIEW_ELEMS (BB * TT * NN * 3)   // 589824

// ---- global scratch (static; no allocation) ----
__device__ unsigned g_flag[BB][BLOCKS_PER_GROUP];  // per-half-block epoch flags
__device__ float    g_xI[2][BB][NN];               // double-buffered I vector

__global__ void reset_kernel() {
    if (threadIdx.x < BB * BLOCKS_PER_GROUP)
        reinterpret_cast<unsigned*>(g_flag)[threadIdx.x] = 0u;
}

__device__ __forceinline__ void load_row(const float* __restrict__ params,
                                         size_t rindex, int lane,
                                         float2 v[8], float& p01) {
    const float* prow = params + rindex * (size_t)PROW;
    p01 = (lane < 2) ? prow[lane] : 0.0f;
    // prow+2 is 8-byte aligned for every row (row stride 2056 B, +8).
    const float2* prow2 = reinterpret_cast<const float2*>(prow + 2);
#pragma unroll
    for (int k = 0; k < 8; ++k) v[k] = prow2[lane + 32 * k];
}

// softmax of one row held in v[]; also extracts beta/gamma from p01.
__device__ __forceinline__ void softmax_row(float2 v[8], float p01,
                                            float& beta, float& gamma) {
    float p0 = __shfl_sync(0xffffffffu, p01, 0);
    float p1 = __shfl_sync(0xffffffffu, p01, 1);
    beta  = 1.0f / (1.0f + __expf(-p0));
    gamma = 1.0f / (1.0f + __expf(-p1));

    float m = -1e30f;
#pragma unroll
    for (int k = 0; k < 8; ++k) m = fmaxf(m, fmaxf(v[k].x, v[k].y));
#pragma unroll
    for (int off = 16; off; off >>= 1)
        m = fmaxf(m, __shfl_xor_sync(0xffffffffu, m, off));

    float sum = 0.0f;
#pragma unroll
    for (int k = 0; k < 8; ++k) {
        v[k].x = __expf(v[k].x - m);
        v[k].y = __expf(v[k].y - m);
        sum += v[k].x + v[k].y;
    }
#pragma unroll
    for (int off = 16; off; off >>= 1)
        sum += __shfl_xor_sync(0xffffffffu, sum, off);
    float inv = 1.0f / sum;
#pragma unroll
    for (int k = 0; k < 8; ++k) { v[k].x *= inv; v[k].y *= inv; }
}

__device__ __forceinline__ void store_epi(float* __restrict__ erow,
                                          const float2 v[8], int lane,
                                          float beta, float gamma) {
    if (lane == 0)
        *reinterpret_cast<float2*>(erow) = make_float2(beta, gamma);
    float2* erow2 = reinterpret_cast<float2*>(erow + 2);
#pragma unroll
    for (int k = 0; k < 8; ++k)
        erow2[lane + 32 * k] = v[k];
}

__global__ void __launch_bounds__(THREADS, 1)
ssir_kernel(const float* __restrict__ x0,
            const float* __restrict__ params,
            float* __restrict__ out) {
    const int j    = blockIdx.x;           // 0..31 (block within group)
    const int gpair = blockIdx.y;          // 0..1
    const int warp = threadIdx.x >> 5;
    const int lane = threadIdx.x & 31;
    const int h    = warp >> 3;            // half: 0 or 1
    const int wg   = warp & 7;             // warp within half
    const int b    = gpair * 2 + h;        // this half's b-group
    const int barid = 1 + h;               // named barrier id (1 or 2)

    const int n0 = j * 16 + wg * 2;        // two adjacent rows per warp

    float* outv = out;                     // output_view region
    float* oute = out + OUT_VIEW_ELEMS;    // epiparams region

    const size_t rbase0 = ((size_t)b * TT) * NN + (size_t)n0;
    const size_t rbase1 = rbase0 + 1;

    // Scan state (registers, redundant across lanes).
    const float* xr0 = x0 + ((size_t)b * NN + n0) * 3;
    float S0 = xr0[0], I0 = xr0[1], R0 = xr0[2];
    float S1 = xr0[3], I1 = xr0[4], R1 = xr0[5];

    // Prefetch t=0 rows.
    float2 v0[8], v1[8];
    float p01_0, p01_1;
    load_row(params, rbase0, lane, v0, p01_0);
    load_row(params, rbase1, lane, v1, p01_1);

    for (int t = 0; t < TT; ++t) {
        // ---------- prefetch t+1 first ----------
        float2 vn0[8], vn1[8];
        float q0 = 0.0f, q1 = 0.0f;
        if (t + 1 < TT) {
            load_row(params, rbase0 + (size_t)(t + 1) * NN, lane, vn0, q0);
            load_row(params, rbase1 + (size_t)(t + 1) * NN, lane, vn1, q1);
        }

        // ---------- shadow work (scan-independent) ----------
        float beta0, gamma0, beta1, gamma1;
        softmax_row(v0, p01_0, beta0, gamma0);
        softmax_row(v1, p01_1, beta1, gamma1);

        const size_t ri0 = rbase0 + (size_t)t * NN;
        const size_t ri1 = rbase1 + (size_t)t * NN;
        store_epi(oute + ri0 * (size_t)PROW, v0, lane, beta0, gamma0);
        store_epi(oute + ri1 * (size_t)PROW, v1, lane, beta1, gamma1);

        // ---------- critical path (per-half sync domain) ----------
        float dot0 = 0.0f, dot1 = 0.0f;
        if (t > 0) {
            if (wg == 0) {
                unsigned r;
                do {
                    asm volatile("ld.acquire.gpu.global.u32 %0, [%1];"
                                 : "=r"(r)
                                 : "l"(&g_flag[b][lane]) : "memory");
                } while (__any_sync(0xffffffffu, r < (unsigned)t));
            }
            asm volatile("bar.sync %0, 256;" :: "r"(barid) : "memory");

            const float2* Ip = reinterpret_cast<const float2*>(g_xI[t & 1][b]);
#pragma unroll
            for (int k = 0; k < 8; ++k) {
                float2 iv = Ip[lane + 32 * k];
                dot0 += v0[k].x * iv.x + v0[k].y * iv.y;
                dot1 += v1[k].x * iv.x + v1[k].y * iv.y;
            }
        } else {
#pragma unroll
            for (int k = 0; k < 8; ++k) {
                int i0 = 2 * (lane + 32 * k);
                float ix = x0[((size_t)b * NN + i0) * 3 + 1];
                float iy = x0[((size_t)b * NN + i0 + 1) * 3 + 1];
                dot0 += v0[k].x * ix + v0[k].y * iy;
                dot1 += v1[k].x * ix + v1[k].y * iy;
            }
        }
#pragma unroll
        for (int off = 16; off; off >>= 1) {
            dot0 += __shfl_xor_sync(0xffffffffu, dot0, off);
            dot1 += __shfl_xor_sync(0xffffffffu, dot1, off);
        }

        // Row 0 update
        {
            float Npop = fmaxf(S0 + I0 + R0, EPSV);
            float dS = -((beta0 * S0) / Npop) * dot0;
            float gI = gamma0 * I0;
            float St = fmaxf(S0 + dS, 0.0f);
            float It = fmaxf(I0 - dS - gI, 0.0f);
            float Rt = fmaxf(R0 + gI, 0.0f);
            float scale = Npop / fmaxf(St + It + Rt, EPSV);
            S0 = St * scale; I0 = It * scale; R0 = Rt * scale;
        }
        // Row 1 update
        {
            float Npop = fmaxf(S1 + I1 + R1, EPSV);
            float dS = -((beta1 * S1) / Npop) * dot1;
            float gI = gamma1 * I1;
            float St = fmaxf(S1 + dS, 0.0f);
            float It = fmaxf(I1 - dS - gI, 0.0f);
            float Rt = fmaxf(R1 + gI, 0.0f);
            float scale = Npop / fmaxf(St + It + Rt, EPSV);
            S1 = St * scale; I1 = It * scale; R1 = Rt * scale;
        }

        // output_view rows: lanes 0-2 row n0, lanes 4-6 row n0+1
        if (lane < 3) {
            float ov = (lane == 0) ? S0 : ((lane == 1) ? I0 : R0);
            outv[ri0 * 3 + lane] = ov;
        } else if (lane >= 4 && lane < 7) {
            int l = lane - 4;
            float ov = (l == 0) ? S1 : ((l == 1) ? I1 : R1);
            outv[ri1 * 3 + l] = ov;
        }

        if (t + 1 < TT) {
            if (lane == 0)
                *reinterpret_cast<float2*>(&g_xI[(t + 1) & 1][b][n0]) =
                    make_float2(I0, I1);
            asm volatile("bar.sync %0, 256;" :: "r"(barid) : "memory");
            if (wg == 0 && lane == 0) {
                __threadfence();
                asm volatile("st.release.gpu.global.u32 [%0], %1;"
                             :: "l"(&g_flag[b][j]), "r"((unsigned)(t + 1))
                             : "memory");
            }
        }

        // Rotate prefetch pipeline.
#pragma unroll
        for (int k = 0; k < 8; ++k) { v0[k] = vn0[k]; v1[k] = vn1[k]; }
        p01_0 = q0;
        p01_1 = q1;
    }
}

extern "C" void kernel_launch(void* const* d_in, const int* in_sizes, int n_in,
                              void* d_out, int out_size) {
    (void)in_sizes; (void)n_in; (void)out_size;
    const float* x0     = (const float*)d_in[0];
    const float* params = (const float*)d_in[1];
    float* out = (float*)d_out;

    reset_kernel<<<1, 128>>>();

    // 64 blocks: blockIdx.y selects b-pair {0,1} or {2,3}; each block hosts
    // two independent named-barrier halves (warps 0-7 -> b, 8-15 -> b+1).
    dim3 grid(BLOCKS_PER_GROUP, 2);
    ssir_kernel<<<grid, THREADS>>>(x0, params, out);
}